// round 13
// baseline (speedup 1.0000x reference)
#include <cuda_runtime.h>
#include <cstdint>

// SlidingGaussianWindow1d: out[b,w,c,d] = clip(corrcoef_t of x[b,t,:] * W[w,t])
// B=16, T=256, C=64, NWIN=224.
//
// Identities:
//  - W[w,t] = A[(t + S_w) mod 256], S_w = (w+1)(w-222)/2
//  - A = conv(gauss, box)/max ~0 outside a ~40-wide arc: truncate t-loop to
//    the support (scanned per-CTA; chunked fallback for wide alpha).
//  - corr_cd = (S_cd - m_c m_d/T) * dinv_c * dinv_d (1/(T-1) cancels)
//  - conv(gw, box)[n] = P[min(n-112,255)] - P[n-144], P = prefix-sum(gw)
//
// R13: single fused kernel. Each CTA computes the window table in smem
// (exp -> warp-scan prefix sum -> windowed diff -> max-normalize -> ballot
// support scan), then runs the R12 mma.sync.m16n8k16.bf16 split-Gram
// (S ~= HtH + HtL + LtH) with STS.128 build and 2x2 warp tiling.

#define T_LEN 256
#define C_DIM 64
#define NWIN  224
#define B_DIM 16
#define KCH   48            // K-chunk (padded); support arc fits in one chunk
#define HSTB  112           // Ht/Lt row stride in bytes (16B-aligned, 7x16)

// ---------------------------------------------------------------------------
__device__ __forceinline__ void mma_bf16(float* d, const uint32_t* a, const uint32_t* b) {
    asm volatile(
        "mma.sync.aligned.m16n8k16.row.col.f32.bf16.bf16.f32 "
        "{%0,%1,%2,%3}, {%4,%5,%6,%7}, {%8,%9}, {%0,%1,%2,%3};"
        : "+f"(d[0]), "+f"(d[1]), "+f"(d[2]), "+f"(d[3])
        : "r"(a[0]), "r"(a[1]), "r"(a[2]), "r"(a[3]), "r"(b[0]), "r"(b[1]));
}
__device__ __forceinline__ void ldmx4(uint32_t* r, uint32_t addr) {
    asm volatile("ldmatrix.sync.aligned.m8n8.x4.shared.b16 {%0,%1,%2,%3}, [%4];"
                 : "=r"(r[0]), "=r"(r[1]), "=r"(r[2]), "=r"(r[3]) : "r"(addr));
}
__device__ __forceinline__ void sts128(uint32_t addr, uint32_t v0, uint32_t v1,
                                       uint32_t v2, uint32_t v3) {
    asm volatile("st.shared.v4.b32 [%0], {%1,%2,%3,%4};"
                 :: "r"(addr), "r"(v0), "r"(v1), "r"(v2), "r"(v3));
}

// ---------------------------------------------------------------------------
// 128 threads per (w, b). Warp grid 2x2: warp wid owns the
// (m32 = (wid&1)*32, n32 = (wid>>1)*32) block of S. 3 mma chains: HH, HL, LH.
// Operands Ht/Lt: bf16 [c][k] rows, stride 112B, built straight from gmem.
// ---------------------------------------------------------------------------
__global__ __launch_bounds__(128, 8) void corr_kernel(const float* __restrict__ x,
                                                      float* __restrict__ out) {
    __shared__ __align__(16) uint32_t Hts[(64 * HSTB) / 4];  // 7 KB (prep scratch: gw,P)
    __shared__ __align__(16) uint32_t Lts[(64 * HSTB) / 4];  // 7 KB (prep scratch: Ac)
    __shared__ float sA[256];
    __shared__ float mpart[2][64];
    __shared__ float mcol[64];
    __shared__ float dinv[64];
    __shared__ float wred[4];
    __shared__ unsigned int masks[8];
    __shared__ int s_ilo, s_keff;

    const int w    = blockIdx.x;
    const int b    = blockIdx.y;
    const int tid  = threadIdx.x;
    const int wid  = tid >> 5;
    const int lane = tid & 31;
    const int g    = lane >> 2;          // fragment group row (0..7)
    const int tig  = lane & 3;           // thread-in-group

    // ======================= fused prep: window table =======================
    {
        float* gw = (float*)Hts;         // [0,256)
        float* P  = gw + 256;            // [256,512)
        float* Ac = (float*)Lts;         // [0,512)

        // gw[t] = exp(-(t-128)^2) * 1/(2 a^2), pair owned by this thread
        float alpha = x[0];              // placeholder; replaced below
        (void)alpha;
        // NOTE: alpha passed via second input; read through out-of-band pointer
        // (set in kernel_launch as __grid_constant__-style param below).
        // -- actual alpha handling: see kernel parameter `alf`.
        gw[0] = 0.0f;                    // dummy to keep smem live (overwritten)
    }
    // (prep implemented below with alpha parameter)

    // ---- placeholder end; real code continues in corr_kernel2 ----
    // (This kernel is never launched; see corr_main below.)
    if (tid == 0x7fffffff) out[0] = x[0] + wid + lane + g + tig + w + b +
        sA[0] + mpart[0][0] + mcol[0] + dinv[0] + wred[0] + masks[0] + s_ilo + s_keff;
}

// ---------------------------------------------------------------------------
// Real kernel (with alpha parameter).
// ---------------------------------------------------------------------------
__global__ __launch_bounds__(128, 8) void corr_main(const float* __restrict__ x,
                                                    const float* __restrict__ alf,
                                                    float* __restrict__ out) {
    __shared__ __align__(16) uint32_t Hts[(64 * HSTB) / 4];  // 7 KB
    __shared__ __align__(16) uint32_t Lts[(64 * HSTB) / 4];  // 7 KB
    __shared__ float sA[256];
    __shared__ float mpart[2][64];
    __shared__ float mcol[64];
    __shared__ float dinv[64];
    __shared__ float wred[4];
    __shared__ unsigned int masks[8];

    const int w    = blockIdx.x;
    const int b    = blockIdx.y;
    const int tid  = threadIdx.x;
    const int wid  = tid >> 5;
    const int lane = tid & 31;
    const int g    = lane >> 2;
    const int tig  = lane & 3;

    // ======================= fused prep =======================
    {
        float* P  = (float*)Hts;         // prefix sums, [0,256)
        float* Ac = (float*)Lts;         // conv values, [0,512)

        float a = alf[0];
        float inv = 1.0f / (2.0f * a * a);
        // pair of gaussian values owned by this thread
        float d0 = (float)(2 * tid)     - 128.0f;
        float d1 = (float)(2 * tid + 1) - 128.0f;
        float g0 = expf(-d0 * d0) * inv;
        float g1 = expf(-d1 * d1) * inv;
        float sp = g0 + g1;

        // warp-inclusive scan of pair sums
        float sc = sp;
        #pragma unroll
        for (int off = 1; off < 32; off <<= 1) {
            float o = __shfl_up_sync(0xFFFFFFFFu, sc, off);
            if (lane >= off) sc += o;
        }
        if (lane == 31) wred[wid] = sc;
        __syncthreads();
        float woff = 0.0f;
        #pragma unroll
        for (int k = 0; k < 4; k++) woff += (k < wid) ? wred[k] : 0.0f;
        float Eex = woff + sc - sp;      // exclusive prefix of pair sums
        P[2 * tid]     = Eex + g0;       // inclusive P
        P[2 * tid + 1] = Eex + sp;
        __syncthreads();

        // conv entries n = 4*tid + u; max over all
        float mx = 0.0f;
        #pragma unroll
        for (int u = 0; u < 4; u++) {
            int n = 4 * tid + u;
            float v = 0.0f;
            if (n < 511 && n >= 112 && n <= 398) {
                int hi = n - 112; if (hi > 255) hi = 255;
                float ph = P[hi];
                float pl = (n >= 144) ? P[n - 144] : 0.0f;
                v = ph - pl;
            }
            if (n < 511) Ac[n] = v;
            mx = fmaxf(mx, v);
        }
        #pragma unroll
        for (int off = 16; off > 0; off >>= 1)
            mx = fmaxf(mx, __shfl_xor_sync(0xFFFFFFFFu, mx, off));
        if (lane == 0) wred[wid] = mx;
        __syncthreads();
        mx = fmaxf(fmaxf(wred[0], wred[1]), fmaxf(wred[2], wred[3]));
        float rinv = 1.0f / mx;

        // A[t] = Ac[128+t]/max, two entries per thread; ballot support
        float a0 = Ac[128 + tid] * rinv;
        float a1 = Ac[256 + tid] * rinv;
        __syncthreads();                 // Ac reads done before Lts reused
        sA[tid]       = a0;
        sA[tid + 128] = a1;
        unsigned int m0 = __ballot_sync(0xFFFFFFFFu, a0 > 1e-6f);
        unsigned int m1 = __ballot_sync(0xFFFFFFFFu, a1 > 1e-6f);
        if (lane == 0) { masks[wid] = m0; masks[wid + 4] = m1; }
        __syncthreads();
    }
    int ilo = 0, keff;
    {
        int hi = 255;
        #pragma unroll
        for (int k = 0; k < 8; k++)
            if (masks[k]) { ilo = k * 32 + __ffs(masks[k]) - 1; break; }
        #pragma unroll
        for (int k = 7; k >= 0; k--)
            if (masks[k]) { hi = k * 32 + 31 - __clz(masks[k]); break; }
        keff = hi - ilo + 1;
    }

    // ======================= main =======================
    int s = ((w + 1) * (w - 222)) / 2;   // cumulative roll (even product, exact)
    int smod = ((s % 256) + 256) & 255;

    const float* xb = x + ((size_t)b << 14);
    const int mb = (wid & 1) << 5;       // warp m-base
    const int nb = (wid >> 1) << 5;      // warp n-base

    const uint32_t htb = (uint32_t)__cvta_generic_to_shared(&Hts[0]);
    const uint32_t ltb = (uint32_t)__cvta_generic_to_shared(&Lts[0]);
    const uint32_t LH  = ltb - htb;

    const int matA = lane >> 3;
    const uint32_t offA0 = (uint32_t)((mb + (lane & 7) + (matA & 1) * 8) * HSTB
                                      + (matA >> 1) * 16);
    const uint32_t offB0 = (uint32_t)((nb + (lane & 7) + (lane >> 4) * 8) * HSTB
                                      + ((lane >> 3) & 1) * 16);

    float D[2][4][4];
    #pragma unroll
    for (int mt = 0; mt < 2; mt++)
        #pragma unroll
        for (int nt = 0; nt < 4; nt++)
            #pragma unroll
            for (int e = 0; e < 4; e++) D[mt][nt][e] = 0.0f;
    float msum = 0.0f;

    const int csp = tid & 63;            // build row
    const int ksp = tid >> 6;            // build k-half (24 k each)

    for (int base = 0; base < keff; base += KCH) {
        int jn = keff - base; if (jn > KCH) jn = KCH;
        __syncthreads();                 // operands free (prep scratch / prior chunk)

        // ---- build Ht/Lt from gmem; packed 16B stores ----
        {
            int t0 = (ilo + base - smod) & 255;
            uint32_t hdst = htb + csp * HSTB + ksp * 48;
            #pragma unroll
            for (int g3 = 0; g3 < 3; g3++) {
                int k0 = ksp * 24 + g3 * 8;
                float y[8];
                #pragma unroll
                for (int u = 0; u < 8; u++) {
                    int j = k0 + u;
                    float v = 0.0f;
                    if (j < jn) {
                        int t = (t0 + j) & 255;
                        v = xb[(t << 6) + csp] * sA[ilo + base + j];
                    }
                    y[u] = v;
                    msum += v;
                }
                uint32_t hp[4], lp[4];
                #pragma unroll
                for (int v2 = 0; v2 < 4; v2++) {
                    float y0 = y[2 * v2], y1 = y[2 * v2 + 1];
                    uint32_t hpv;
                    asm("cvt.rn.bf16x2.f32 %0, %1, %2;" : "=r"(hpv) : "f"(y1), "f"(y0));
                    float h0 = __uint_as_float(hpv << 16);
                    float h1 = __uint_as_float(hpv & 0xFFFF0000u);
                    float l0 = y0 - h0;
                    float l1 = y1 - h1;
                    uint32_t lpv;
                    asm("cvt.rn.bf16x2.f32 %0, %1, %2;" : "=r"(lpv) : "f"(l1), "f"(l0));
                    hp[v2] = hpv;
                    lp[v2] = lpv;
                }
                sts128(hdst + g3 * 16,      hp[0], hp[1], hp[2], hp[3]);
                sts128(hdst + LH + g3 * 16, lp[0], lp[1], lp[2], lp[3]);
            }
        }
        __syncthreads();

        // ---- mma mainloop ----
        int nks = (jn + 15) >> 4;
        #pragma unroll 3
        for (int ks = 0; ks < nks; ks++) {
            uint32_t ko = (uint32_t)(ks << 5);
            uint32_t aH[2][4], aL[2][4];
            ldmx4(aH[0], htb + offA0 + ko);
            ldmx4(aH[1], htb + offA0 + (uint32_t)(16 * HSTB) + ko);
            ldmx4(aL[0], ltb + offA0 + ko);
            ldmx4(aL[1], ltb + offA0 + (uint32_t)(16 * HSTB) + ko);
            #pragma unroll
            for (int bt = 0; bt < 2; bt++) {
                uint32_t bo = offB0 + (uint32_t)(bt * 16 * HSTB) + ko;
                uint32_t bh[4], bl[4];
                ldmx4(bh, htb + bo);
                ldmx4(bl, ltb + bo);
                #pragma unroll
                for (int mt = 0; mt < 2; mt++) {
                    #pragma unroll
                    for (int pr = 0; pr < 2; pr++) {
                        float* Dp = D[mt][bt * 2 + pr];
                        mma_bf16(Dp, aH[mt], bh + 2 * pr);   // H^T H
                        mma_bf16(Dp, aH[mt], bl + 2 * pr);   // H^T L
                        mma_bf16(Dp, aL[mt], bh + 2 * pr);   // L^T H
                    }
                }
            }
        }
    }

    // ---- column sums ----
    mpart[ksp][csp] = msum;
    __syncthreads();
    if (tid < 64) mcol[tid] = mpart[0][tid] + mpart[1][tid];
    __syncthreads();

    // ---- diagonal -> dinv (diag warps: mb == nb, i.e. wid 0 and 3) ----
    const float inv256 = 1.0f / 256.0f;
    if (mb == nb && tig == (g >> 1)) {
        #pragma unroll
        for (int mt = 0; mt < 2; mt++) {
            #pragma unroll
            for (int rh = 0; rh < 2; rh++) {
                int c = mb + mt * 16 + rh * 8 + g;
                int nt = mt * 2 + rh;
                int e  = (g & 1) + rh * 2;
                float m = mcol[c];
                dinv[c] = rsqrtf(D[mt][nt][e] - m * m * inv256);
            }
        }
    }
    __syncthreads();

    // ---- normalize, clip, write ----
    float* ob = out + (((size_t)(b * NWIN + w)) << 12);
    const int d0 = nb + (tig << 1);
    #pragma unroll
    for (int mt = 0; mt < 2; mt++) {
        #pragma unroll
        for (int rh = 0; rh < 2; rh++) {
            int c = mb + mt * 16 + rh * 8 + g;
            float mc = mcol[c] * inv256;
            float dc = dinv[c];
            #pragma unroll
            for (int nt = 0; nt < 4; nt++) {
                int d = d0 + nt * 8;
                float md0 = mcol[d], md1 = mcol[d + 1];
                float dd0 = dinv[d], dd1 = dinv[d + 1];
                float2 v;
                v.x = (D[mt][nt][rh * 2 + 0] - mc * md0) * dc * dd0;
                v.y = (D[mt][nt][rh * 2 + 1] - mc * md1) * dc * dd1;
                v.x = fminf(1.0f, fmaxf(-1.0f, v.x));
                v.y = fminf(1.0f, fmaxf(-1.0f, v.y));
                *(float2*)(ob + (c << 6) + d) = v;
            }
        }
    }
}

// ---------------------------------------------------------------------------
extern "C" void kernel_launch(void* const* d_in, const int* in_sizes, int n_in,
                              void* d_out, int out_size) {
    const float* x     = (const float*)d_in[0];   // (16, 256, 64) fp32
    const float* alpha = (const float*)d_in[1];   // (1,) fp32
    float* out = (float*)d_out;                   // (16, 224, 64, 64) fp32

    dim3 grid(NWIN, B_DIM);
    corr_main<<<grid, 128>>>(x, alpha, out);
}

// round 14
// speedup vs baseline: 1.5821x; 1.5821x over previous
#include <cuda_runtime.h>
#include <cstdint>
#include <cmath>

// SlidingGaussianWindow1d: out[b,w,c,d] = clip(corrcoef_t of x[b,t,:] * W[w,t])
// B=16, T=256, C=64, NWIN=224.
//
// Identities:
//  - W[w,t] = A[(t + S_w) mod 256], S_w = (w+1)(w-222)/2
//  - A = conv(gauss, box)/max is INDEPENDENT of win_alpha (linear scale
//    cancels in the max-normalization) -> computed on HOST, passed as a
//    1KB kernel parameter (constant-bank broadcast reads).
//  - A ~0 outside a ~40-wide arc: t-loop truncated to the support.
//  - corr_cd = (S_cd - m_c m_d/T) * dinv_c * dinv_d (1/(T-1) cancels)
//
// R14: single corr kernel (= R12 core): mma.sync.m16n8k16.bf16 split-Gram
// (y = hi + lo bf16, S ~= HtH + HtL + LtH), STS.128 operand build,
// ldmatrix.x4 fragments, 2x2 warp tiling. Prep kernel deleted.

#define T_LEN 256
#define C_DIM 64
#define NWIN  224
#define B_DIM 16
#define KCH   48            // K-chunk (padded); support arc fits in one chunk
#define HSTB  112           // Ht/Lt row stride in bytes (16B-aligned, 7x16)

struct WinParam {
    float A[256];
    int   ilo;
    int   keff;
};

// ---------------------------------------------------------------------------
__device__ __forceinline__ void mma_bf16(float* d, const uint32_t* a, const uint32_t* b) {
    asm volatile(
        "mma.sync.aligned.m16n8k16.row.col.f32.bf16.bf16.f32 "
        "{%0,%1,%2,%3}, {%4,%5,%6,%7}, {%8,%9}, {%0,%1,%2,%3};"
        : "+f"(d[0]), "+f"(d[1]), "+f"(d[2]), "+f"(d[3])
        : "r"(a[0]), "r"(a[1]), "r"(a[2]), "r"(a[3]), "r"(b[0]), "r"(b[1]));
}
__device__ __forceinline__ void ldmx4(uint32_t* r, uint32_t addr) {
    asm volatile("ldmatrix.sync.aligned.m8n8.x4.shared.b16 {%0,%1,%2,%3}, [%4];"
                 : "=r"(r[0]), "=r"(r[1]), "=r"(r[2]), "=r"(r[3]) : "r"(addr));
}
__device__ __forceinline__ void sts128(uint32_t addr, uint32_t v0, uint32_t v1,
                                       uint32_t v2, uint32_t v3) {
    asm volatile("st.shared.v4.b32 [%0], {%1,%2,%3,%4};"
                 :: "r"(addr), "r"(v0), "r"(v1), "r"(v2), "r"(v3));
}

// ---------------------------------------------------------------------------
// 128 threads per (w, b). Warp grid 2x2: warp wid owns the
// (m32 = (wid&1)*32, n32 = (wid>>1)*32) block of S. 3 mma chains: HH, HL, LH.
// Operands Ht/Lt: bf16 [c][k] rows, stride 112B, built straight from gmem.
// ---------------------------------------------------------------------------
__global__ __launch_bounds__(128, 8) void corr_kernel(const float* __restrict__ x,
                                                      float* __restrict__ out,
                                                      const __grid_constant__ WinParam wp) {
    __shared__ __align__(16) uint32_t Hts[(64 * HSTB) / 4];  // 7 KB
    __shared__ __align__(16) uint32_t Lts[(64 * HSTB) / 4];  // 7 KB
    __shared__ float mpart[2][64];
    __shared__ float mcol[64];
    __shared__ float dinv[64];

    const int w    = blockIdx.x;
    const int b    = blockIdx.y;
    const int tid  = threadIdx.x;
    const int wid  = tid >> 5;
    const int lane = tid & 31;
    const int g    = lane >> 2;          // fragment group row (0..7)
    const int tig  = lane & 3;           // thread-in-group

    int s = ((w + 1) * (w - 222)) / 2;   // cumulative roll (even product, exact)
    int smod = ((s % 256) + 256) & 255;

    const int ilo  = wp.ilo;
    const int keff = wp.keff;

    const float* xb = x + ((size_t)b << 14);
    const int mb = (wid & 1) << 5;       // warp m-base (rows of S)
    const int nb = (wid >> 1) << 5;      // warp n-base (cols of S)

    const uint32_t htb = (uint32_t)__cvta_generic_to_shared(&Hts[0]);
    const uint32_t ltb = (uint32_t)__cvta_generic_to_shared(&Lts[0]);
    const uint32_t LH  = ltb - htb;

    // ldmatrix per-lane offsets (bytes) into the [c][k] buffers.
    // A m16k16 (row-major): matrices {m0k0, m8k0, m0k8, m8k8}
    const int matA = lane >> 3;
    const uint32_t offA0 = (uint32_t)((mb + (lane & 7) + (matA & 1) * 8) * HSTB
                                      + (matA >> 1) * 16);
    // B pair of n8k16 (col-major): matrices {n0k0, n0k8, n8k0, n8k8}
    const uint32_t offB0 = (uint32_t)((nb + (lane & 7) + (lane >> 4) * 8) * HSTB
                                      + ((lane >> 3) & 1) * 16);

    float D[2][4][4];
    #pragma unroll
    for (int mt = 0; mt < 2; mt++)
        #pragma unroll
        for (int nt = 0; nt < 4; nt++)
            #pragma unroll
            for (int e = 0; e < 4; e++) D[mt][nt][e] = 0.0f;
    float msum = 0.0f;

    // build mapping: thread owns row csp, k-half ksp (24 k each)
    const int csp = tid & 63;
    const int ksp = tid >> 6;

    for (int base = 0; base < keff; base += KCH) {
        int jn = keff - base; if (jn > KCH) jn = KCH;
        if (base) __syncthreads();       // guard operand reuse across chunks

        // ---- build Ht/Lt from gmem; packed 16B stores; A via constant bank ----
        {
            int t0 = (ilo + base - smod) & 255;
            uint32_t hdst = htb + csp * HSTB + ksp * 48;
            #pragma unroll
            for (int g3 = 0; g3 < 3; g3++) {
                int k0 = ksp * 24 + g3 * 8;
                float y[8];
                #pragma unroll
                for (int u = 0; u < 8; u++) {
                    int j = k0 + u;
                    float v = 0.0f;
                    if (j < jn) {
                        int t = (t0 + j) & 255;
                        v = xb[(t << 6) + csp] * wp.A[ilo + base + j];
                    }
                    y[u] = v;
                    msum += v;
                }
                uint32_t hp[4], lp[4];
                #pragma unroll
                for (int v2 = 0; v2 < 4; v2++) {
                    float y0 = y[2 * v2], y1 = y[2 * v2 + 1];
                    uint32_t hpv;
                    asm("cvt.rn.bf16x2.f32 %0, %1, %2;" : "=r"(hpv) : "f"(y1), "f"(y0));
                    float h0 = __uint_as_float(hpv << 16);
                    float h1 = __uint_as_float(hpv & 0xFFFF0000u);
                    float l0 = y0 - h0;
                    float l1 = y1 - h1;
                    uint32_t lpv;
                    asm("cvt.rn.bf16x2.f32 %0, %1, %2;" : "=r"(lpv) : "f"(l1), "f"(l0));
                    hp[v2] = hpv;
                    lp[v2] = lpv;
                }
                sts128(hdst + g3 * 16,      hp[0], hp[1], hp[2], hp[3]);
                sts128(hdst + LH + g3 * 16, lp[0], lp[1], lp[2], lp[3]);
            }
        }
        __syncthreads();

        // ---- mma mainloop ----
        int nks = (jn + 15) >> 4;
        #pragma unroll 3
        for (int ks = 0; ks < nks; ks++) {
            uint32_t ko = (uint32_t)(ks << 5);   // 16 k * 2B
            uint32_t aH[2][4], aL[2][4];
            ldmx4(aH[0], htb + offA0 + ko);
            ldmx4(aH[1], htb + offA0 + (uint32_t)(16 * HSTB) + ko);
            ldmx4(aL[0], ltb + offA0 + ko);
            ldmx4(aL[1], ltb + offA0 + (uint32_t)(16 * HSTB) + ko);
            #pragma unroll
            for (int bt = 0; bt < 2; bt++) {
                uint32_t bo = offB0 + (uint32_t)(bt * 16 * HSTB) + ko;
                uint32_t bh[4], bl[4];
                ldmx4(bh, htb + bo);
                ldmx4(bl, ltb + bo);
                #pragma unroll
                for (int mt = 0; mt < 2; mt++) {
                    #pragma unroll
                    for (int pr = 0; pr < 2; pr++) {
                        float* Dp = D[mt][bt * 2 + pr];
                        mma_bf16(Dp, aH[mt], bh + 2 * pr);   // H^T H
                        mma_bf16(Dp, aH[mt], bl + 2 * pr);   // H^T L
                        mma_bf16(Dp, aL[mt], bh + 2 * pr);   // L^T H
                    }
                }
            }
        }
    }

    // ---- column sums ----
    mpart[ksp][csp] = msum;
    __syncthreads();
    if (tid < 64) mcol[tid] = mpart[0][tid] + mpart[1][tid];
    __syncthreads();

    // ---- diagonal -> dinv (diag warps: mb == nb, i.e. wid 0 and 3) ----
    const float inv256 = 1.0f / 256.0f;
    if (mb == nb && tig == (g >> 1)) {
        #pragma unroll
        for (int mt = 0; mt < 2; mt++) {
            #pragma unroll
            for (int rh = 0; rh < 2; rh++) {
                int c = mb + mt * 16 + rh * 8 + g;
                int nt = mt * 2 + rh;
                int e  = (g & 1) + rh * 2;
                float m = mcol[c];
                dinv[c] = rsqrtf(D[mt][nt][e] - m * m * inv256);
            }
        }
    }
    __syncthreads();

    // ---- normalize, clip, write (float2 = 32B L2 sectors per row-segment) ----
    float* ob = out + (((size_t)(b * NWIN + w)) << 12);
    const int d0 = nb + (tig << 1);
    #pragma unroll
    for (int mt = 0; mt < 2; mt++) {
        #pragma unroll
        for (int rh = 0; rh < 2; rh++) {
            int c = mb + mt * 16 + rh * 8 + g;
            float mc = mcol[c] * inv256;
            float dc = dinv[c];
            #pragma unroll
            for (int nt = 0; nt < 4; nt++) {
                int d = d0 + nt * 8;
                float md0 = mcol[d], md1 = mcol[d + 1];
                float dd0 = dinv[d], dd1 = dinv[d + 1];
                float2 v;
                v.x = (D[mt][nt][rh * 2 + 0] - mc * md0) * dc * dd0;
                v.y = (D[mt][nt][rh * 2 + 1] - mc * md1) * dc * dd1;
                v.x = fminf(1.0f, fmaxf(-1.0f, v.x));
                v.y = fminf(1.0f, fmaxf(-1.0f, v.y));
                *(float2*)(ob + (c << 6) + d) = v;
            }
        }
    }
}

// ---------------------------------------------------------------------------
// Host: window table (alpha-independent; scale cancels in normalization).
// Computed in double each call (deterministic, ~20us of CPU only at capture).
// ---------------------------------------------------------------------------
extern "C" void kernel_launch(void* const* d_in, const int* in_sizes, int n_in,
                              void* d_out, int out_size) {
    const float* x = (const float*)d_in[0];       // (16, 256, 64) fp32
    float* out = (float*)d_out;                   // (16, 224, 64, 64) fp32

    WinParam wp;
    {
        double gw[256], P[256];
        double acc = 0.0;
        for (int t = 0; t < 256; t++) {
            double d = (double)t - 128.0;
            gw[t] = exp(-d * d);
            acc += gw[t];
            P[t] = acc;
        }
        // conv(gw, box)[n] = P[min(n-112,255)] - P[n-144] for n in [112,398]
        double Ac[511];
        double mx = 0.0;
        for (int n = 0; n < 511; n++) {
            double v = 0.0;
            if (n >= 112 && n <= 398) {
                int hi = n - 112; if (hi > 255) hi = 255;
                double ph = P[hi];
                double pl = (n >= 144) ? P[n - 144] : 0.0;
                v = ph - pl;
            }
            Ac[n] = v;
            if (v > mx) mx = v;
        }
        int lo = 255, hi = 0;
        for (int t = 0; t < 256; t++) {
            double a = Ac[128 + t] / mx;
            wp.A[t] = (float)a;
            if (a > 1e-6) { if (t < lo) lo = t; if (t > hi) hi = t; }
        }
        if (hi < lo) { lo = 0; hi = 255; }   // degenerate fallback
        wp.ilo  = lo;
        wp.keff = hi - lo + 1;
    }

    dim3 grid(NWIN, B_DIM);
    corr_kernel<<<grid, 128>>>(x, out, wp);
}

// round 15
// speedup vs baseline: 1.6522x; 1.0443x over previous
#include <cuda_runtime.h>
#include <cstdint>
#include <cmath>

// SlidingGaussianWindow1d: out[b,w,c,d] = clip(corrcoef_t of x[b,t,:] * W[w,t])
// B=16, T=256, C=64, NWIN=224.
//
// Identities:
//  - W[w,t] = A[(t + S_w) mod 256], S_w = (w+1)(w-222)/2
//  - A = conv(gauss, box)/max is INDEPENDENT of win_alpha (linear scale
//    cancels in the max-normalization) -> computed on HOST, passed as a
//    1KB kernel parameter (constant-bank broadcast reads).
//  - A ~0 outside a ~40-wide arc: t-loop truncated to the support.
//  - corr_cd = (S_cd - m_c m_d/T) * dinv_c * dinv_d (1/(T-1) cancels)
//
// R15: single-chunk template kernel (NKS compile-time) + smem-staged
// epilogue (scattered STG.64 -> coalesced full-row STG.128 via a 64x272B
// staging tile unioned with the mma operand buffers).

#define T_LEN 256
#define C_DIM 64
#define NWIN  224
#define B_DIM 16
#define KCH   48            // K capacity of operand buffers (48 k, zero-padded)
#define HSTB  112           // Ht/Lt row stride in bytes (16B-aligned, 7x16)
#define CBW   68            // corr staging row stride in words (272B)

struct WinParam {
    float A[256];
    int   ilo;
    int   keff;
};

// ---------------------------------------------------------------------------
__device__ __forceinline__ void mma_bf16(float* d, const uint32_t* a, const uint32_t* b) {
    asm volatile(
        "mma.sync.aligned.m16n8k16.row.col.f32.bf16.bf16.f32 "
        "{%0,%1,%2,%3}, {%4,%5,%6,%7}, {%8,%9}, {%0,%1,%2,%3};"
        : "+f"(d[0]), "+f"(d[1]), "+f"(d[2]), "+f"(d[3])
        : "r"(a[0]), "r"(a[1]), "r"(a[2]), "r"(a[3]), "r"(b[0]), "r"(b[1]));
}
__device__ __forceinline__ void ldmx4(uint32_t* r, uint32_t addr) {
    asm volatile("ldmatrix.sync.aligned.m8n8.x4.shared.b16 {%0,%1,%2,%3}, [%4];"
                 : "=r"(r[0]), "=r"(r[1]), "=r"(r[2]), "=r"(r[3]) : "r"(addr));
}
__device__ __forceinline__ void sts128(uint32_t addr, uint32_t v0, uint32_t v1,
                                       uint32_t v2, uint32_t v3) {
    asm volatile("st.shared.v4.b32 [%0], {%1,%2,%3,%4};"
                 :: "r"(addr), "r"(v0), "r"(v1), "r"(v2), "r"(v3));
}

// ---------------------------------------------------------------------------
// 128 threads per (w, b). Warp grid 2x2: warp wid owns the
// (m32 = (wid&1)*32, n32 = (wid>>1)*32) block of S. 3 mma chains: HH, HL, LH.
// Operands Ht/Lt: bf16 [c][k] rows, stride 112B, built straight from gmem.
// NKS = number of k16 steps (keff <= 16*NKS <= 48), compile-time.
// ---------------------------------------------------------------------------
template <int NKS>
__global__ __launch_bounds__(128, 8) void corr_tmpl(const float* __restrict__ x,
                                                    float* __restrict__ out,
                                                    const __grid_constant__ WinParam wp) {
    // union: [mma phase] Ht (1792 w) + Lt (1792 w) | [epilogue] 64x68-word corr tile
    __shared__ __align__(16) uint32_t SMEMU[64 * CBW];   // 17408 B
    __shared__ float mpart[2][64];
    __shared__ float mcol[64];
    __shared__ float dinv[64];

    const int w    = blockIdx.x;
    const int b    = blockIdx.y;
    const int tid  = threadIdx.x;
    const int wid  = tid >> 5;
    const int lane = tid & 31;
    const int g    = lane >> 2;          // fragment group row (0..7)
    const int tig  = lane & 3;           // thread-in-group

    int s = ((w + 1) * (w - 222)) / 2;   // cumulative roll (even product, exact)
    int smod = ((s % 256) + 256) & 255;

    const int ilo = wp.ilo;
    const int jn  = wp.keff;             // <= 16*NKS

    const float* xb = x + ((size_t)b << 14);
    const int mb = (wid & 1) << 5;       // warp m-base (rows of S)
    const int nb = (wid >> 1) << 5;      // warp n-base (cols of S)

    const uint32_t htb = (uint32_t)__cvta_generic_to_shared(&SMEMU[0]);
    const uint32_t ltb = htb + (uint32_t)(16 * HSTB * 4);   // 7168 B
    const uint32_t LH  = ltb - htb;

    // ldmatrix per-lane offsets (bytes) into the [c][k] buffers.
    const int matA = lane >> 3;
    const uint32_t offA0 = (uint32_t)((mb + (lane & 7) + (matA & 1) * 8) * HSTB
                                      + (matA >> 1) * 16);
    const uint32_t offB0 = (uint32_t)((nb + (lane & 7) + (lane >> 4) * 8) * HSTB
                                      + ((lane >> 3) & 1) * 16);

    float D[2][4][4];
    #pragma unroll
    for (int mt = 0; mt < 2; mt++)
        #pragma unroll
        for (int nt = 0; nt < 4; nt++)
            #pragma unroll
            for (int e = 0; e < 4; e++) D[mt][nt][e] = 0.0f;
    float msum = 0.0f;

    // build mapping: thread owns row csp, k-half ksp (24 k each)
    const int csp = tid & 63;
    const int ksp = tid >> 6;

    // ---- build Ht/Lt from gmem; packed 16B stores; A via constant bank ----
    {
        int t0 = (ilo - smod) & 255;
        uint32_t hdst = htb + csp * HSTB + ksp * 48;
        #pragma unroll
        for (int g3 = 0; g3 < 3; g3++) {
            int k0 = ksp * 24 + g3 * 8;
            float y[8];
            #pragma unroll
            for (int u = 0; u < 8; u++) {
                int j = k0 + u;
                float v = 0.0f;
                if (j < jn) {
                    int t = (t0 + j) & 255;
                    v = xb[(t << 6) + csp] * wp.A[ilo + j];
                }
                y[u] = v;
                msum += v;
            }
            uint32_t hp[4], lp[4];
            #pragma unroll
            for (int v2 = 0; v2 < 4; v2++) {
                float y0 = y[2 * v2], y1 = y[2 * v2 + 1];
                uint32_t hpv;
                asm("cvt.rn.bf16x2.f32 %0, %1, %2;" : "=r"(hpv) : "f"(y1), "f"(y0));
                float h0 = __uint_as_float(hpv << 16);
                float h1 = __uint_as_float(hpv & 0xFFFF0000u);
                float l0 = y0 - h0;
                float l1 = y1 - h1;
                uint32_t lpv;
                asm("cvt.rn.bf16x2.f32 %0, %1, %2;" : "=r"(lpv) : "f"(l1), "f"(l0));
                hp[v2] = hpv;
                lp[v2] = lpv;
            }
            sts128(hdst + g3 * 16,      hp[0], hp[1], hp[2], hp[3]);
            sts128(hdst + LH + g3 * 16, lp[0], lp[1], lp[2], lp[3]);
        }
    }
    __syncthreads();

    // ---- mma mainloop (fully unrolled, NKS k-steps) ----
    #pragma unroll
    for (int ks = 0; ks < NKS; ks++) {
        uint32_t ko = (uint32_t)(ks << 5);   // 16 k * 2B
        uint32_t aH[2][4], aL[2][4];
        ldmx4(aH[0], htb + offA0 + ko);
        ldmx4(aH[1], htb + offA0 + (uint32_t)(16 * HSTB) + ko);
        ldmx4(aL[0], ltb + offA0 + ko);
        ldmx4(aL[1], ltb + offA0 + (uint32_t)(16 * HSTB) + ko);
        #pragma unroll
        for (int bt = 0; bt < 2; bt++) {
            uint32_t bo = offB0 + (uint32_t)(bt * 16 * HSTB) + ko;
            uint32_t bh[4], bl[4];
            ldmx4(bh, htb + bo);
            ldmx4(bl, ltb + bo);
            #pragma unroll
            for (int mt = 0; mt < 2; mt++) {
                #pragma unroll
                for (int pr = 0; pr < 2; pr++) {
                    float* Dp = D[mt][bt * 2 + pr];
                    mma_bf16(Dp, aH[mt], bh + 2 * pr);   // H^T H
                    mma_bf16(Dp, aH[mt], bl + 2 * pr);   // H^T L
                    mma_bf16(Dp, aL[mt], bh + 2 * pr);   // L^T H
                }
            }
        }
    }

    // ---- column sums ----
    mpart[ksp][csp] = msum;
    __syncthreads();
    if (tid < 64) mcol[tid] = mpart[0][tid] + mpart[1][tid];
    __syncthreads();

    // ---- diagonal -> dinv (diag warps: mb == nb, i.e. wid 0 and 3) ----
    const float inv256 = 1.0f / 256.0f;
    if (mb == nb && tig == (g >> 1)) {
        #pragma unroll
        for (int mt = 0; mt < 2; mt++) {
            #pragma unroll
            for (int rh = 0; rh < 2; rh++) {
                int c = mb + mt * 16 + rh * 8 + g;
                int nt = mt * 2 + rh;
                int e  = (g & 1) + rh * 2;
                float m = mcol[c];
                dinv[c] = rsqrtf(D[mt][nt][e] - m * m * inv256);
            }
        }
    }
    __syncthreads();

    // ---- normalize + clip into smem staging tile (stride 68 words) ----
    float* cb = (float*)SMEMU;           // union reuse: mma reads all complete
    const int d0 = nb + (tig << 1);
    #pragma unroll
    for (int mt = 0; mt < 2; mt++) {
        #pragma unroll
        for (int rh = 0; rh < 2; rh++) {
            int c = mb + mt * 16 + rh * 8 + g;
            float mc = mcol[c] * inv256;
            float dc = dinv[c];
            #pragma unroll
            for (int nt = 0; nt < 4; nt++) {
                int d = d0 + nt * 8;
                float md0 = mcol[d], md1 = mcol[d + 1];
                float dd0 = dinv[d], dd1 = dinv[d + 1];
                float2 v;
                v.x = (D[mt][nt][rh * 2 + 0] - mc * md0) * dc * dd0;
                v.y = (D[mt][nt][rh * 2 + 1] - mc * md1) * dc * dd1;
                v.x = fminf(1.0f, fmaxf(-1.0f, v.x));
                v.y = fminf(1.0f, fmaxf(-1.0f, v.y));
                *(float2*)(cb + c * CBW + d) = v;
            }
        }
    }
    __syncthreads();

    // ---- stream out: full coalesced rows, 512B per warp op ----
    float* ob = out + (((size_t)(b * NWIN + w)) << 12);
    #pragma unroll
    for (int p = 0; p < 8; p++) {
        int idx = (p << 7) + tid;        // 0..1023 float4 slots
        int r   = idx >> 4;
        int c4  = (idx & 15) << 2;
        float4 v = *(float4*)(cb + r * CBW + c4);
        *(float4*)(ob + (r << 6) + c4) = v;
    }
}

// ---------------------------------------------------------------------------
// Fallback: generic chunked kernel (keff > 48; never hit for alpha=0.5).
// ---------------------------------------------------------------------------
__global__ __launch_bounds__(128, 8) void corr_gen(const float* __restrict__ x,
                                                   float* __restrict__ out,
                                                   const __grid_constant__ WinParam wp) {
    __shared__ __align__(16) uint32_t Hts[(64 * HSTB) / 4];
    __shared__ __align__(16) uint32_t Lts[(64 * HSTB) / 4];
    __shared__ float mpart[2][64];
    __shared__ float mcol[64];
    __shared__ float dinv[64];

    const int w    = blockIdx.x;
    const int b    = blockIdx.y;
    const int tid  = threadIdx.x;
    const int wid  = tid >> 5;
    const int lane = tid & 31;
    const int g    = lane >> 2;
    const int tig  = lane & 3;

    int s = ((w + 1) * (w - 222)) / 2;
    int smod = ((s % 256) + 256) & 255;
    const int ilo  = wp.ilo;
    const int keff = wp.keff;

    const float* xb = x + ((size_t)b << 14);
    const int mb = (wid & 1) << 5;
    const int nb = (wid >> 1) << 5;

    const uint32_t htb = (uint32_t)__cvta_generic_to_shared(&Hts[0]);
    const uint32_t ltb = (uint32_t)__cvta_generic_to_shared(&Lts[0]);
    const uint32_t LH  = ltb - htb;

    const int matA = lane >> 3;
    const uint32_t offA0 = (uint32_t)((mb + (lane & 7) + (matA & 1) * 8) * HSTB
                                      + (matA >> 1) * 16);
    const uint32_t offB0 = (uint32_t)((nb + (lane & 7) + (lane >> 4) * 8) * HSTB
                                      + ((lane >> 3) & 1) * 16);

    float D[2][4][4];
    #pragma unroll
    for (int mt = 0; mt < 2; mt++)
        #pragma unroll
        for (int nt = 0; nt < 4; nt++)
            #pragma unroll
            for (int e = 0; e < 4; e++) D[mt][nt][e] = 0.0f;
    float msum = 0.0f;

    const int csp = tid & 63;
    const int ksp = tid >> 6;

    for (int base = 0; base < keff; base += KCH) {
        int jn = keff - base; if (jn > KCH) jn = KCH;
        if (base) __syncthreads();
        {
            int t0 = (ilo + base - smod) & 255;
            uint32_t hdst = htb + csp * HSTB + ksp * 48;
            #pragma unroll
            for (int g3 = 0; g3 < 3; g3++) {
                int k0 = ksp * 24 + g3 * 8;
                float y[8];
                #pragma unroll
                for (int u = 0; u < 8; u++) {
                    int j = k0 + u;
                    float v = 0.0f;
                    if (j < jn) {
                        int t = (t0 + j) & 255;
                        v = xb[(t << 6) + csp] * wp.A[ilo + base + j];
                    }
                    y[u] = v;
                    msum += v;
                }
                uint32_t hp[4], lp[4];
                #pragma unroll
                for (int v2 = 0; v2 < 4; v2++) {
                    float y0 = y[2 * v2], y1 = y[2 * v2 + 1];
                    uint32_t hpv;
                    asm("cvt.rn.bf16x2.f32 %0, %1, %2;" : "=r"(hpv) : "f"(y1), "f"(y0));
                    float h0 = __uint_as_float(hpv << 16);
                    float h1 = __uint_as_float(hpv & 0xFFFF0000u);
                    float l0 = y0 - h0;
                    float l1 = y1 - h1;
                    uint32_t lpv;
                    asm("cvt.rn.bf16x2.f32 %0, %1, %2;" : "=r"(lpv) : "f"(l1), "f"(l0));
                    hp[v2] = hpv;
                    lp[v2] = lpv;
                }
                sts128(hdst + g3 * 16,      hp[0], hp[1], hp[2], hp[3]);
                sts128(hdst + LH + g3 * 16, lp[0], lp[1], lp[2], lp[3]);
            }
        }
        __syncthreads();

        int nks = (jn + 15) >> 4;
        #pragma unroll 3
        for (int ks = 0; ks < nks; ks++) {
            uint32_t ko = (uint32_t)(ks << 5);
            uint32_t aH[2][4], aL[2][4];
            ldmx4(aH[0], htb + offA0 + ko);
            ldmx4(aH[1], htb + offA0 + (uint32_t)(16 * HSTB) + ko);
            ldmx4(aL[0], ltb + offA0 + ko);
            ldmx4(aL[1], ltb + offA0 + (uint32_t)(16 * HSTB) + ko);
            #pragma unroll
            for (int bt = 0; bt < 2; bt++) {
                uint32_t bo = offB0 + (uint32_t)(bt * 16 * HSTB) + ko;
                uint32_t bh[4], bl[4];
                ldmx4(bh, htb + bo);
                ldmx4(bl, ltb + bo);
                #pragma unroll
                for (int mt = 0; mt < 2; mt++) {
                    #pragma unroll
                    for (int pr = 0; pr < 2; pr++) {
                        float* Dp = D[mt][bt * 2 + pr];
                        mma_bf16(Dp, aH[mt], bh + 2 * pr);
                        mma_bf16(Dp, aH[mt], bl + 2 * pr);
                        mma_bf16(Dp, aL[mt], bh + 2 * pr);
                    }
                }
            }
        }
    }

    mpart[ksp][csp] = msum;
    __syncthreads();
    if (tid < 64) mcol[tid] = mpart[0][tid] + mpart[1][tid];
    __syncthreads();

    const float inv256 = 1.0f / 256.0f;
    if (mb == nb && tig == (g >> 1)) {
        #pragma unroll
        for (int mt = 0; mt < 2; mt++) {
            #pragma unroll
            for (int rh = 0; rh < 2; rh++) {
                int c = mb + mt * 16 + rh * 8 + g;
                int nt = mt * 2 + rh;
                int e  = (g & 1) + rh * 2;
                float m = mcol[c];
                dinv[c] = rsqrtf(D[mt][nt][e] - m * m * inv256);
            }
        }
    }
    __syncthreads();

    float* ob = out + (((size_t)(b * NWIN + w)) << 12);
    const int d0 = nb + (tig << 1);
    #pragma unroll
    for (int mt = 0; mt < 2; mt++) {
        #pragma unroll
        for (int rh = 0; rh < 2; rh++) {
            int c = mb + mt * 16 + rh * 8 + g;
            float mc = mcol[c] * inv256;
            float dc = dinv[c];
            #pragma unroll
            for (int nt = 0; nt < 4; nt++) {
                int d = d0 + nt * 8;
                float md0 = mcol[d], md1 = mcol[d + 1];
                float dd0 = dinv[d], dd1 = dinv[d + 1];
                float2 v;
                v.x = (D[mt][nt][rh * 2 + 0] - mc * md0) * dc * dd0;
                v.y = (D[mt][nt][rh * 2 + 1] - mc * md1) * dc * dd1;
                v.x = fminf(1.0f, fmaxf(-1.0f, v.x));
                v.y = fminf(1.0f, fmaxf(-1.0f, v.y));
                *(float2*)(ob + (c << 6) + d) = v;
            }
        }
    }
}

// ---------------------------------------------------------------------------
// Host: window table (alpha-independent; scale cancels in normalization).
// ---------------------------------------------------------------------------
extern "C" void kernel_launch(void* const* d_in, const int* in_sizes, int n_in,
                              void* d_out, int out_size) {
    const float* x = (const float*)d_in[0];       // (16, 256, 64) fp32
    float* out = (float*)d_out;                   // (16, 224, 64, 64) fp32

    WinParam wp;
    {
        double gw[256], P[256];
        double acc = 0.0;
        for (int t = 0; t < 256; t++) {
            double d = (double)t - 128.0;
            gw[t] = exp(-d * d);
            acc += gw[t];
            P[t] = acc;
        }
        double Ac[511];
        double mx = 0.0;
        for (int n = 0; n < 511; n++) {
            double v = 0.0;
            if (n >= 112 && n <= 398) {
                int hi = n - 112; if (hi > 255) hi = 255;
                double ph = P[hi];
                double pl = (n >= 144) ? P[n - 144] : 0.0;
                v = ph - pl;
            }
            Ac[n] = v;
            if (v > mx) mx = v;
        }
        int lo = 255, hi = 0;
        for (int t = 0; t < 256; t++) {
            double a = Ac[128 + t] / mx;
            wp.A[t] = (float)a;
            if (a > 1e-6) { if (t < lo) lo = t; if (t > hi) hi = t; }
        }
        if (hi < lo) { lo = 0; hi = 255; }
        wp.ilo  = lo;
        wp.keff = hi - lo + 1;
    }

    dim3 grid(NWIN, B_DIM);
    if (wp.keff <= 16)      corr_tmpl<1><<<grid, 128>>>(x, out, wp);
    else if (wp.keff <= 32) corr_tmpl<2><<<grid, 128>>>(x, out, wp);
    else if (wp.keff <= 48) corr_tmpl<3><<<grid, 128>>>(x, out, wp);
    else                    corr_gen<<<grid, 128>>>(x, out, wp);
}